// round 8
// baseline (speedup 1.0000x reference)
#include <cuda_runtime.h>
#include <cuda_bf16.h>
#include <cstdint>
#include <math.h>

#define DIM 4096
#define BM 128
#define BN 128
#define BK 64                         // 64 bf16 = 128B rows -> SW128 swizzle
#define NKITER (DIM / BK)             // 64
#define NSTAGE 3
#define TILE_BYTES 16384              // 128 rows x 128B
#define STAGE_BYTES (4 * TILE_BYTES)  // Ahi, Alo, Bhi, Blo
#define SMEM_DYN (NSTAGE * STAGE_BYTES)   // 192 KB
#define EPSF 0.01f

// ---------------- scratch (device globals: allocation-free rule) -------------
__device__ __nv_bfloat16 g_xhi[(size_t)DIM * DIM];
__device__ __nv_bfloat16 g_xlo[(size_t)DIM * DIM];
__device__ __nv_bfloat16 g_whi[(size_t)DIM * DIM];
__device__ __nv_bfloat16 g_wlo[(size_t)DIM * DIM];
__device__ __nv_bfloat16 g_ghi[(size_t)DIM * DIM];
__device__ __nv_bfloat16 g_glo[(size_t)DIM * DIM];
__device__ __nv_bfloat16 g_hhi[(size_t)DIM * DIM];
__device__ __nv_bfloat16 g_hlo[(size_t)DIM * DIM];

// ---------------- PTX helpers (sm_80-baseline features only) -----------------
static __device__ __forceinline__ uint32_t smem_u32(const void* p) {
    uint32_t a;
    asm("{ .reg .u64 t; cvta.to.shared.u64 t, %1; cvt.u32.u64 %0, t; }"
        : "=r"(a) : "l"(p));
    return a;
}

static __device__ __forceinline__ void cp16(uint32_t d, const void* g) {
    asm volatile("cp.async.cg.shared.global [%0], [%1], 16;" :: "r"(d), "l"(g) : "memory");
}

static __device__ __forceinline__ void ldsm4(uint32_t& r0, uint32_t& r1,
                                             uint32_t& r2, uint32_t& r3, uint32_t a) {
    asm volatile("ldmatrix.sync.aligned.m8n8.x4.shared.b16 {%0,%1,%2,%3}, [%4];"
                 : "=r"(r0), "=r"(r1), "=r"(r2), "=r"(r3) : "r"(a));
}

#define MMA16816(acc, a, b0, b1)                                                \
    asm volatile("mma.sync.aligned.m16n8k16.row.col.f32.bf16.bf16.f32 "         \
                 "{%0,%1,%2,%3}, {%4,%5,%6,%7}, {%8,%9}, {%0,%1,%2,%3};"        \
                 : "+f"((acc)[0]), "+f"((acc)[1]), "+f"((acc)[2]), "+f"((acc)[3])\
                 : "r"((a)[0]), "r"((a)[1]), "r"((a)[2]), "r"((a)[3]),          \
                   "r"(b0), "r"(b1))

// SW128 swizzle: addr = row*128 + (col ^ ((row&7)<<4)) within a tile
// (equivalent to bo ^ ((bo>>3)&0x70) for 128B rows)

// Load one 128-row x 64-bf16 (128B/row) tile into SW128-swizzled SMEM.
static __device__ __forceinline__ void load_tile(uint32_t tb,
                                                 const __nv_bfloat16* __restrict__ src,
                                                 int r0, int k0, int tid) {
#pragma unroll
    for (int i = 0; i < 4; ++i) {
        int q = tid + i * 256;           // 1024 16B chunks per tile
        int r = q >> 3, j = q & 7;
        const __nv_bfloat16* gp = src + (size_t)(r0 + r) * DIM + (k0 + j * 8);
        uint32_t bo = (uint32_t)(r * 128 + j * 16);
        cp16(tb + (bo ^ ((bo >> 3) & 0x70u)), gp);
    }
}

static __device__ __forceinline__ void prefetch_stage(
    uint32_t sbase, int it,
    const __nv_bfloat16* __restrict__ Ahi, const __nv_bfloat16* __restrict__ Alo,
    const __nv_bfloat16* __restrict__ Bhi, const __nv_bfloat16* __restrict__ Blo,
    int m0, int n0, int tid) {
    if (it < NKITER) {
        uint32_t sb = sbase + (uint32_t)(it % NSTAGE) * STAGE_BYTES;
        int k0 = it * BK;
        load_tile(sb,                  Ahi, m0, k0, tid);
        load_tile(sb + TILE_BYTES,     Alo, m0, k0, tid);
        load_tile(sb + 2 * TILE_BYTES, Bhi, n0, k0, tid);
        load_tile(sb + 3 * TILE_BYTES, Blo, n0, k0, tid);
    }
    asm volatile("cp.async.commit_group;" ::: "memory");  // uniform group accounting
}

// ---------------- fused GEMM: D = Ahi*Bhi^T + Ahi*Blo^T + Alo*Bhi^T ----------
// MODE 0: epilogue h = acc + bias; write bf16 hi/lo split (for second GEMM)
// MODE 1: epilogue z = acc + bias; c = cos(z); flip if |c| < EPS; write fp32
template <int MODE>
__global__ void __launch_bounds__(256, 1)
fused_gemm(const __nv_bfloat16* __restrict__ Ahi, const __nv_bfloat16* __restrict__ Alo,
           const __nv_bfloat16* __restrict__ Bhi, const __nv_bfloat16* __restrict__ Blo,
           const float* __restrict__ bias,
           float* __restrict__ outF,
           __nv_bfloat16* __restrict__ outHi, __nv_bfloat16* __restrict__ outLo) {
    extern __shared__ __align__(1024) char smem_raw[];
    const uint32_t sbase = smem_u32(smem_raw);

    const int tid  = threadIdx.x;
    const int wid  = tid >> 5;
    const int lane = tid & 31;

    // L2-friendly rasterization: groups of 8 M-tiles sweep across N
    const int GRID_N = DIM / BN;       // 32
    const int GROUP  = 8;
    const int width  = GROUP * GRID_N; // 256
    int pid  = blockIdx.x;
    int gidx = pid / width;
    int pin  = pid % width;
    const int m0 = (gidx * GROUP + (pin % GROUP)) * BM;
    const int n0 = (pin / GROUP) * BN;

    // warp layout: 2 (M) x 4 (N); warp tile 64 x 32
    const int wm = wid >> 2;           // 0..1
    const int wn = wid & 3;            // 0..3

    // ldmatrix per-lane addressing (same pattern for A and B tiles):
    //   row_in_tile = frag_base + (lane & 15), col_bytes = (lane>>4)*16 + s*32
    const int lr = lane & 15;
    const uint32_t ccol = (uint32_t)((lane >> 4) * 16);

    // A fragment row terms (per mfrag), B row terms (per nfrag-pair)
    uint32_t arow_term[4], axor[4];
#pragma unroll
    for (int f = 0; f < 4; ++f) {
        int ar = wm * 64 + f * 16 + lr;
        arow_term[f] = (uint32_t)(ar * 128);
        axor[f] = (uint32_t)((ar & 7) << 4);
    }
    uint32_t brow_term[2], bxor[2];
#pragma unroll
    for (int p = 0; p < 2; ++p) {
        int br = wn * 32 + p * 16 + lr;
        brow_term[p] = (uint32_t)(br * 128);
        bxor[p] = (uint32_t)((br & 7) << 4);
    }

    float acc[4][4][4];
#pragma unroll
    for (int f = 0; f < 4; ++f)
#pragma unroll
        for (int nf = 0; nf < 4; ++nf)
#pragma unroll
            for (int e = 0; e < 4; ++e) acc[f][nf][e] = 0.0f;

    prefetch_stage(sbase, 0, Ahi, Alo, Bhi, Blo, m0, n0, tid);
    prefetch_stage(sbase, 1, Ahi, Alo, Bhi, Blo, m0, n0, tid);

    for (int it = 0; it < NKITER; ++it) {
        prefetch_stage(sbase, it + 2, Ahi, Alo, Bhi, Blo, m0, n0, tid);
        asm volatile("cp.async.wait_group 2;" ::: "memory");   // stage 'it' resident
        __syncthreads();

        const uint32_t sb   = sbase + (uint32_t)(it % NSTAGE) * STAGE_BYTES;
        const uint32_t sAhi = sb;
        const uint32_t sAlo = sb + TILE_BYTES;
        const uint32_t sBhi = sb + 2 * TILE_BYTES;
        const uint32_t sBlo = sb + 3 * TILE_BYTES;

#pragma unroll
        for (int s = 0; s < 4; ++s) {                      // 4 x K=16 per BK=64
            const uint32_t cs = ccol + (uint32_t)(s * 32);
            // B fragments: 2 pairs x (hi, lo)
            uint32_t bh[2][4], bl[2][4];
#pragma unroll
            for (int p = 0; p < 2; ++p) {
                uint32_t off = brow_term[p] + (cs ^ bxor[p]);
                ldsm4(bh[p][0], bh[p][1], bh[p][2], bh[p][3], sBhi + off);
                ldsm4(bl[p][0], bl[p][1], bl[p][2], bl[p][3], sBlo + off);
            }
#pragma unroll
            for (int f = 0; f < 4; ++f) {
                uint32_t off = arow_term[f] + (cs ^ axor[f]);
                uint32_t ah[4], al[4];
                ldsm4(ah[0], ah[1], ah[2], ah[3], sAhi + off);
                ldsm4(al[0], al[1], al[2], al[3], sAlo + off);
#pragma unroll
                for (int nf = 0; nf < 4; ++nf) {
                    const int p = nf >> 1, o = nf & 1;     // even nf: {r0,r2}; odd: {r1,r3}
                    const uint32_t bh0 = bh[p][o], bh1 = bh[p][o + 2];
                    const uint32_t bl0 = bl[p][o], bl1 = bl[p][o + 2];
                    MMA16816(acc[f][nf], ah, bh0, bh1);
                    MMA16816(acc[f][nf], ah, bl0, bl1);
                    MMA16816(acc[f][nf], al, bh0, bh1);
                }
            }
        }
        __syncthreads();   // all reads of stage 'it' done before it gets refilled
    }

    // ---------------- epilogue (register -> global, no smem needed) ----------
    const int qrow = lane >> 2;            // 0..7
    const int qcol = (lane & 3) * 2;       // 0,2,4,6
#pragma unroll
    for (int f = 0; f < 4; ++f) {
#pragma unroll
        for (int nf = 0; nf < 4; ++nf) {
            const int col  = n0 + wn * 32 + nf * 8 + qcol;
            const int row0 = m0 + wm * 64 + f * 16 + qrow;
            const float2 bb = *reinterpret_cast<const float2*>(bias + col);
            float v00 = acc[f][nf][0] + bb.x;
            float v01 = acc[f][nf][1] + bb.y;
            float v10 = acc[f][nf][2] + bb.x;
            float v11 = acc[f][nf][3] + bb.y;
            size_t gi0 = (size_t)row0 * DIM + col;
            size_t gi1 = gi0 + (size_t)8 * DIM;
            if (MODE == 0) {
                __nv_bfloat16 h00 = __float2bfloat16(v00);
                __nv_bfloat16 h01 = __float2bfloat16(v01);
                __nv_bfloat16 h10 = __float2bfloat16(v10);
                __nv_bfloat16 h11 = __float2bfloat16(v11);
                __nv_bfloat162 hp0; hp0.x = h00; hp0.y = h01;
                __nv_bfloat162 hp1; hp1.x = h10; hp1.y = h11;
                __nv_bfloat162 lp0;
                lp0.x = __float2bfloat16(v00 - __bfloat162float(h00));
                lp0.y = __float2bfloat16(v01 - __bfloat162float(h01));
                __nv_bfloat162 lp1;
                lp1.x = __float2bfloat16(v10 - __bfloat162float(h10));
                lp1.y = __float2bfloat16(v11 - __bfloat162float(h11));
                *reinterpret_cast<__nv_bfloat162*>(outHi + gi0) = hp0;
                *reinterpret_cast<__nv_bfloat162*>(outHi + gi1) = hp1;
                *reinterpret_cast<__nv_bfloat162*>(outLo + gi0) = lp0;
                *reinterpret_cast<__nv_bfloat162*>(outLo + gi1) = lp1;
            } else {
                float c00 = cosf(v00); c00 = (fabsf(c00) < EPSF) ? -c00 : c00;
                float c01 = cosf(v01); c01 = (fabsf(c01) < EPSF) ? -c01 : c01;
                float c10 = cosf(v10); c10 = (fabsf(c10) < EPSF) ? -c10 : c10;
                float c11 = cosf(v11); c11 = (fabsf(c11) < EPSF) ? -c11 : c11;
                float2 o0 = make_float2(c00, c01);
                float2 o1 = make_float2(c10, c11);
                *reinterpret_cast<float2*>(outF + gi0) = o0;
                *reinterpret_cast<float2*>(outF + gi1) = o1;
            }
        }
    }
}

// ---------------- fp32 -> bf16 hi/lo splitter --------------------------------
__global__ void __launch_bounds__(256) split_bf16x2(
    const float* __restrict__ src, __nv_bfloat16* __restrict__ hi,
    __nv_bfloat16* __restrict__ lo, int n4) {
    int i = blockIdx.x * blockDim.x + threadIdx.x;
    if (i >= n4) return;
    float4 v = reinterpret_cast<const float4*>(src)[i];
    __nv_bfloat16 h0 = __float2bfloat16(v.x);
    __nv_bfloat16 h1 = __float2bfloat16(v.y);
    __nv_bfloat16 h2 = __float2bfloat16(v.z);
    __nv_bfloat16 h3 = __float2bfloat16(v.w);
    __nv_bfloat16 l0 = __float2bfloat16(v.x - __bfloat162float(h0));
    __nv_bfloat16 l1 = __float2bfloat16(v.y - __bfloat162float(h1));
    __nv_bfloat16 l2 = __float2bfloat16(v.z - __bfloat162float(h2));
    __nv_bfloat16 l3 = __float2bfloat16(v.w - __bfloat162float(h3));
    uint2 hp, lp;
    hp.x = (uint32_t)__bfloat16_as_ushort(h0) | ((uint32_t)__bfloat16_as_ushort(h1) << 16);
    hp.y = (uint32_t)__bfloat16_as_ushort(h2) | ((uint32_t)__bfloat16_as_ushort(h3) << 16);
    lp.x = (uint32_t)__bfloat16_as_ushort(l0) | ((uint32_t)__bfloat16_as_ushort(l1) << 16);
    lp.y = (uint32_t)__bfloat16_as_ushort(l2) | ((uint32_t)__bfloat16_as_ushort(l3) << 16);
    reinterpret_cast<uint2*>(hi)[i] = hp;
    reinterpret_cast<uint2*>(lo)[i] = lp;
}

// ---------------- launch -----------------------------------------------------
extern "C" void kernel_launch(void* const* d_in, const int* in_sizes, int n_in,
                              void* d_out, int out_size) {
    const float* x  = (const float*)d_in[0];
    const float* W  = (const float*)d_in[1];
    const float* b  = (const float*)d_in[2];
    const float* g  = (const float*)d_in[3];
    const float* gb = (const float*)d_in[4];
    float* out = (float*)d_out;

    __nv_bfloat16 *xhi, *xlo, *whi, *wlo, *ghi, *glo, *hhi, *hlo;
    cudaGetSymbolAddress((void**)&xhi, g_xhi);
    cudaGetSymbolAddress((void**)&xlo, g_xlo);
    cudaGetSymbolAddress((void**)&whi, g_whi);
    cudaGetSymbolAddress((void**)&wlo, g_wlo);
    cudaGetSymbolAddress((void**)&ghi, g_ghi);
    cudaGetSymbolAddress((void**)&glo, g_glo);
    cudaGetSymbolAddress((void**)&hhi, g_hhi);
    cudaGetSymbolAddress((void**)&hlo, g_hlo);

    const int n4 = (int)((size_t)DIM * DIM / 4);   // 4,194,304
    split_bf16x2<<<n4 / 256, 256>>>(x, xhi, xlo, n4);
    split_bf16x2<<<n4 / 256, 256>>>(W, whi, wlo, n4);
    split_bf16x2<<<n4 / 256, 256>>>(g, ghi, glo, n4);

    cudaFuncSetAttribute(fused_gemm<0>, cudaFuncAttributeMaxDynamicSharedMemorySize, SMEM_DYN);
    cudaFuncSetAttribute(fused_gemm<1>, cudaFuncAttributeMaxDynamicSharedMemorySize, SMEM_DYN);

    const int grid = (DIM / BM) * (DIM / BN);      // 1024
    fused_gemm<0><<<grid, 256, SMEM_DYN>>>(xhi, xlo, whi, wlo, b, nullptr, hhi, hlo);
    fused_gemm<1><<<grid, 256, SMEM_DYN>>>(hhi, hlo, ghi, glo, gb, out, nullptr, nullptr);
}

// round 13
// speedup vs baseline: 1.0545x; 1.0545x over previous
#include <cuda_runtime.h>
#include <cuda_bf16.h>
#include <cstdint>
#include <math.h>

#define DIM 4096
#define BM 128
#define BN 128
#define BK 32                         // 32 bf16 = 64B rows -> SW64 swizzle
#define NKITER (DIM / BK)             // 128
#define NSTAGE 3
#define TILE_BYTES 8192               // 128 rows x 64B
#define STAGE_BYTES (4 * TILE_BYTES)  // Ahi, Alo, Bhi, Blo = 32KB
#define SMEM_DYN (NSTAGE * STAGE_BYTES)   // 96 KB -> 2 CTAs/SM
#define EPSF 0.01f

// ---------------- scratch (device globals: allocation-free rule) -------------
__device__ __nv_bfloat16 g_xhi[(size_t)DIM * DIM];
__device__ __nv_bfloat16 g_xlo[(size_t)DIM * DIM];
__device__ __nv_bfloat16 g_whi[(size_t)DIM * DIM];
__device__ __nv_bfloat16 g_wlo[(size_t)DIM * DIM];
__device__ __nv_bfloat16 g_ghi[(size_t)DIM * DIM];
__device__ __nv_bfloat16 g_glo[(size_t)DIM * DIM];
__device__ __nv_bfloat16 g_hhi[(size_t)DIM * DIM];
__device__ __nv_bfloat16 g_hlo[(size_t)DIM * DIM];

// ---------------- PTX helpers (sm_80-baseline features only) -----------------
static __device__ __forceinline__ uint32_t smem_u32(const void* p) {
    uint32_t a;
    asm("{ .reg .u64 t; cvta.to.shared.u64 t, %1; cvt.u32.u64 %0, t; }"
        : "=r"(a) : "l"(p));
    return a;
}

static __device__ __forceinline__ void cp16(uint32_t d, const void* g) {
    asm volatile("cp.async.cg.shared.global [%0], [%1], 16;" :: "r"(d), "l"(g) : "memory");
}

static __device__ __forceinline__ void ldsm4(uint32_t& r0, uint32_t& r1,
                                             uint32_t& r2, uint32_t& r3, uint32_t a) {
    asm volatile("ldmatrix.sync.aligned.m8n8.x4.shared.b16 {%0,%1,%2,%3}, [%4];"
                 : "=r"(r0), "=r"(r1), "=r"(r2), "=r"(r3) : "r"(a));
}

#define MMA16816(acc, a, b0, b1)                                                \
    asm volatile("mma.sync.aligned.m16n8k16.row.col.f32.bf16.bf16.f32 "         \
                 "{%0,%1,%2,%3}, {%4,%5,%6,%7}, {%8,%9}, {%0,%1,%2,%3};"        \
                 : "+f"((acc)[0]), "+f"((acc)[1]), "+f"((acc)[2]), "+f"((acc)[3])\
                 : "r"((a)[0]), "r"((a)[1]), "r"((a)[2]), "r"((a)[3]),          \
                   "r"(b0), "r"(b1))

// SW64 swizzle for 64B rows: bo ^ ((bo>>3) & 0x30)  (xor pattern ((row>>1)&3)<<4)

// Load one 128-row x 32-bf16 (64B/row) tile into SW64-swizzled SMEM.
static __device__ __forceinline__ void load_tile(uint32_t tb,
                                                 const __nv_bfloat16* __restrict__ src,
                                                 int r0, int k0, int tid) {
#pragma unroll
    for (int i = 0; i < 2; ++i) {
        int q = tid + i * 256;           // 512 16B chunks per tile
        int r = q >> 2, j = q & 3;
        const __nv_bfloat16* gp = src + (size_t)(r0 + r) * DIM + (k0 + j * 8);
        uint32_t bo = (uint32_t)(r * 64 + j * 16);
        cp16(tb + (bo ^ ((bo >> 3) & 0x30u)), gp);
    }
}

static __device__ __forceinline__ void prefetch_stage(
    uint32_t sbase, int it,
    const __nv_bfloat16* __restrict__ Ahi, const __nv_bfloat16* __restrict__ Alo,
    const __nv_bfloat16* __restrict__ Bhi, const __nv_bfloat16* __restrict__ Blo,
    int m0, int n0, int tid) {
    if (it < NKITER) {
        uint32_t sb = sbase + (uint32_t)(it % NSTAGE) * STAGE_BYTES;
        int k0 = it * BK;
        load_tile(sb,                  Ahi, m0, k0, tid);
        load_tile(sb + TILE_BYTES,     Alo, m0, k0, tid);
        load_tile(sb + 2 * TILE_BYTES, Bhi, n0, k0, tid);
        load_tile(sb + 3 * TILE_BYTES, Blo, n0, k0, tid);
    }
    asm volatile("cp.async.commit_group;" ::: "memory");  // uniform group accounting
}

// ---------------- fused GEMM: D = Ahi*Bhi^T + Ahi*Blo^T + Alo*Bhi^T ----------
// MODE 0: epilogue h = acc + bias; write bf16 hi/lo split (for second GEMM)
// MODE 1: epilogue z = acc + bias; c = cos(z); flip if |c| < EPS; write fp32
template <int MODE>
__global__ void __launch_bounds__(256, 2)
fused_gemm(const __nv_bfloat16* __restrict__ Ahi, const __nv_bfloat16* __restrict__ Alo,
           const __nv_bfloat16* __restrict__ Bhi, const __nv_bfloat16* __restrict__ Blo,
           const float* __restrict__ bias,
           float* __restrict__ outF,
           __nv_bfloat16* __restrict__ outHi, __nv_bfloat16* __restrict__ outLo) {
    extern __shared__ __align__(1024) char smem_raw[];
    const uint32_t sbase = smem_u32(smem_raw);

    const int tid  = threadIdx.x;
    const int wid  = tid >> 5;
    const int lane = tid & 31;

    // L2-friendly rasterization: groups of 8 M-tiles sweep across N
    const int GRID_N = DIM / BN;       // 32
    const int GROUP  = 8;
    const int width  = GROUP * GRID_N; // 256
    int pid  = blockIdx.x;
    int gidx = pid / width;
    int pin  = pid % width;
    const int m0 = (gidx * GROUP + (pin % GROUP)) * BM;
    const int n0 = (pin / GROUP) * BN;

    // warp layout: 2 (M) x 4 (N); warp tile 64 x 32
    const int wm = wid >> 2;           // 0..1
    const int wn = wid & 3;            // 0..3

    // ldmatrix per-lane addressing:
    //   row_in_tile = frag_base + (lane & 15), col_bytes = (lane>>4)*16 + s*32
    const int lr = lane & 15;
    const uint32_t ccol = (uint32_t)((lane >> 4) * 16);

    uint32_t arow_term[4], axor[4];
#pragma unroll
    for (int f = 0; f < 4; ++f) {
        int ar = wm * 64 + f * 16 + lr;
        arow_term[f] = (uint32_t)(ar * 64);
        axor[f] = (uint32_t)(((ar >> 1) & 3) << 4);
    }
    uint32_t brow_term[2], bxor[2];
#pragma unroll
    for (int p = 0; p < 2; ++p) {
        int br = wn * 32 + p * 16 + lr;
        brow_term[p] = (uint32_t)(br * 64);
        bxor[p] = (uint32_t)(((br >> 1) & 3) << 4);
    }

    float acc[4][4][4];
#pragma unroll
    for (int f = 0; f < 4; ++f)
#pragma unroll
        for (int nf = 0; nf < 4; ++nf)
#pragma unroll
            for (int e = 0; e < 4; ++e) acc[f][nf][e] = 0.0f;

    prefetch_stage(sbase, 0, Ahi, Alo, Bhi, Blo, m0, n0, tid);
    prefetch_stage(sbase, 1, Ahi, Alo, Bhi, Blo, m0, n0, tid);

    for (int it = 0; it < NKITER; ++it) {
        asm volatile("cp.async.wait_group 1;" ::: "memory");   // stage 'it' resident
        __syncthreads();   // also: all warps done reading stage it-1 -> refill safe

        const uint32_t sb   = sbase + (uint32_t)(it % NSTAGE) * STAGE_BYTES;
        const uint32_t sAhi = sb;
        const uint32_t sAlo = sb + TILE_BYTES;
        const uint32_t sBhi = sb + 2 * TILE_BYTES;
        const uint32_t sBlo = sb + 3 * TILE_BYTES;

#pragma unroll
        for (int s = 0; s < 2; ++s) {                      // 2 x K=16 per BK=32
            const uint32_t cs = ccol + (uint32_t)(s * 32);
            uint32_t bh[2][4], bl[2][4];
#pragma unroll
            for (int p = 0; p < 2; ++p) {
                uint32_t off = brow_term[p] + (cs ^ bxor[p]);
                ldsm4(bh[p][0], bh[p][1], bh[p][2], bh[p][3], sBhi + off);
                ldsm4(bl[p][0], bl[p][1], bl[p][2], bl[p][3], sBlo + off);
            }
#pragma unroll
            for (int f = 0; f < 4; ++f) {
                uint32_t off = arow_term[f] + (cs ^ axor[f]);
                uint32_t ah[4], al[4];
                ldsm4(ah[0], ah[1], ah[2], ah[3], sAhi + off);
                ldsm4(al[0], al[1], al[2], al[3], sAlo + off);
#pragma unroll
                for (int nf = 0; nf < 4; ++nf) {
                    const int p = nf >> 1, o = nf & 1;
                    const uint32_t bh0 = bh[p][o], bh1 = bh[p][o + 2];
                    const uint32_t bl0 = bl[p][o], bl1 = bl[p][o + 2];
                    MMA16816(acc[f][nf], ah, bh0, bh1);
                    MMA16816(acc[f][nf], ah, bl0, bl1);
                    MMA16816(acc[f][nf], al, bh0, bh1);
                }
            }
        }
        // prefetch AFTER barrier: stage (it+2)%3 == (it-1)%3, whose readers all
        // passed this iteration's __syncthreads already.
        prefetch_stage(sbase, it + 2, Ahi, Alo, Bhi, Blo, m0, n0, tid);
    }
    asm volatile("cp.async.wait_group 0;" ::: "memory");

    // ---------------- epilogue (register -> global) --------------------------
    const int qrow = lane >> 2;            // 0..7
    const int qcol = (lane & 3) * 2;       // 0,2,4,6
#pragma unroll
    for (int f = 0; f < 4; ++f) {
#pragma unroll
        for (int nf = 0; nf < 4; ++nf) {
            const int col  = n0 + wn * 32 + nf * 8 + qcol;
            const int row0 = m0 + wm * 64 + f * 16 + qrow;
            const float2 bb = *reinterpret_cast<const float2*>(bias + col);
            float v00 = acc[f][nf][0] + bb.x;
            float v01 = acc[f][nf][1] + bb.y;
            float v10 = acc[f][nf][2] + bb.x;
            float v11 = acc[f][nf][3] + bb.y;
            size_t gi0 = (size_t)row0 * DIM + col;
            size_t gi1 = gi0 + (size_t)8 * DIM;
            if (MODE == 0) {
                __nv_bfloat16 h00 = __float2bfloat16(v00);
                __nv_bfloat16 h01 = __float2bfloat16(v01);
                __nv_bfloat16 h10 = __float2bfloat16(v10);
                __nv_bfloat16 h11 = __float2bfloat16(v11);
                __nv_bfloat162 hp0; hp0.x = h00; hp0.y = h01;
                __nv_bfloat162 hp1; hp1.x = h10; hp1.y = h11;
                __nv_bfloat162 lp0;
                lp0.x = __float2bfloat16(v00 - __bfloat162float(h00));
                lp0.y = __float2bfloat16(v01 - __bfloat162float(h01));
                __nv_bfloat162 lp1;
                lp1.x = __float2bfloat16(v10 - __bfloat162float(h10));
                lp1.y = __float2bfloat16(v11 - __bfloat162float(h11));
                *reinterpret_cast<__nv_bfloat162*>(outHi + gi0) = hp0;
                *reinterpret_cast<__nv_bfloat162*>(outHi + gi1) = hp1;
                *reinterpret_cast<__nv_bfloat162*>(outLo + gi0) = lp0;
                *reinterpret_cast<__nv_bfloat162*>(outLo + gi1) = lp1;
            } else {
                float c00 = cosf(v00); c00 = (fabsf(c00) < EPSF) ? -c00 : c00;
                float c01 = cosf(v01); c01 = (fabsf(c01) < EPSF) ? -c01 : c01;
                float c10 = cosf(v10); c10 = (fabsf(c10) < EPSF) ? -c10 : c10;
                float c11 = cosf(v11); c11 = (fabsf(c11) < EPSF) ? -c11 : c11;
                float2 o0 = make_float2(c00, c01);
                float2 o1 = make_float2(c10, c11);
                *reinterpret_cast<float2*>(outF + gi0) = o0;
                *reinterpret_cast<float2*>(outF + gi1) = o1;
            }
        }
    }
}

// ---------------- fp32 -> bf16 hi/lo splitter --------------------------------
__global__ void __launch_bounds__(256) split_bf16x2(
    const float* __restrict__ src, __nv_bfloat16* __restrict__ hi,
    __nv_bfloat16* __restrict__ lo, int n4) {
    int i = blockIdx.x * blockDim.x + threadIdx.x;
    if (i >= n4) return;
    float4 v = reinterpret_cast<const float4*>(src)[i];
    __nv_bfloat16 h0 = __float2bfloat16(v.x);
    __nv_bfloat16 h1 = __float2bfloat16(v.y);
    __nv_bfloat16 h2 = __float2bfloat16(v.z);
    __nv_bfloat16 h3 = __float2bfloat16(v.w);
    __nv_bfloat16 l0 = __float2bfloat16(v.x - __bfloat162float(h0));
    __nv_bfloat16 l1 = __float2bfloat16(v.y - __bfloat162float(h1));
    __nv_bfloat16 l2 = __float2bfloat16(v.z - __bfloat162float(h2));
    __nv_bfloat16 l3 = __float2bfloat16(v.w - __bfloat162float(h3));
    uint2 hp, lp;
    hp.x = (uint32_t)__bfloat16_as_ushort(h0) | ((uint32_t)__bfloat16_as_ushort(h1) << 16);
    hp.y = (uint32_t)__bfloat16_as_ushort(h2) | ((uint32_t)__bfloat16_as_ushort(h3) << 16);
    lp.x = (uint32_t)__bfloat16_as_ushort(l0) | ((uint32_t)__bfloat16_as_ushort(l1) << 16);
    lp.y = (uint32_t)__bfloat16_as_ushort(l2) | ((uint32_t)__bfloat16_as_ushort(l3) << 16);
    reinterpret_cast<uint2*>(hi)[i] = hp;
    reinterpret_cast<uint2*>(lo)[i] = lp;
}

// ---------------- launch -----------------------------------------------------
extern "C" void kernel_launch(void* const* d_in, const int* in_sizes, int n_in,
                              void* d_out, int out_size) {
    const float* x  = (const float*)d_in[0];
    const float* W  = (const float*)d_in[1];
    const float* b  = (const float*)d_in[2];
    const float* g  = (const float*)d_in[3];
    const float* gb = (const float*)d_in[4];
    float* out = (float*)d_out;

    __nv_bfloat16 *xhi, *xlo, *whi, *wlo, *ghi, *glo, *hhi, *hlo;
    cudaGetSymbolAddress((void**)&xhi, g_xhi);
    cudaGetSymbolAddress((void**)&xlo, g_xlo);
    cudaGetSymbolAddress((void**)&whi, g_whi);
    cudaGetSymbolAddress((void**)&wlo, g_wlo);
    cudaGetSymbolAddress((void**)&ghi, g_ghi);
    cudaGetSymbolAddress((void**)&glo, g_glo);
    cudaGetSymbolAddress((void**)&hhi, g_hhi);
    cudaGetSymbolAddress((void**)&hlo, g_hlo);

    const int n4 = (int)((size_t)DIM * DIM / 4);   // 4,194,304
    split_bf16x2<<<n4 / 256, 256>>>(x, xhi, xlo, n4);
    split_bf16x2<<<n4 / 256, 256>>>(W, whi, wlo, n4);
    split_bf16x2<<<n4 / 256, 256>>>(g, ghi, glo, n4);

    cudaFuncSetAttribute(fused_gemm<0>, cudaFuncAttributeMaxDynamicSharedMemorySize, SMEM_DYN);
    cudaFuncSetAttribute(fused_gemm<1>, cudaFuncAttributeMaxDynamicSharedMemorySize, SMEM_DYN);

    const int grid = (DIM / BM) * (DIM / BN);      // 1024
    fused_gemm<0><<<grid, 256, SMEM_DYN>>>(xhi, xlo, whi, wlo, b, nullptr, hhi, hlo);
    fused_gemm<1><<<grid, 256, SMEM_DYN>>>(hhi, hlo, ghi, glo, gb, out, nullptr, nullptr);
}

// round 16
// speedup vs baseline: 1.1663x; 1.1060x over previous
#include <cuda_runtime.h>
#include <cuda_bf16.h>
#include <cstdint>
#include <math.h>

#define DIM 4096
#define BM 128
#define BN 128
#define BK 32                         // 32 bf16 = 64B rows -> SW64 swizzle
#define NKITER (DIM / BK)             // 128
#define NROUND (NKITER / 3)           // 42 full rounds, 2 tail iters
#define TILE_BYTES 8192               // 128 rows x 64B
#define STAGE_BYTES (4 * TILE_BYTES)  // Ahi, Alo, Bhi, Blo = 32KB
#define SMEM_STAGES (3 * STAGE_BYTES) // 96 KB
#define SMEM_DYN (SMEM_STAGES + 64)   // + mbarriers -> still 2 CTAs/SM
#define EPSF 0.01f

// ---------------- scratch (device globals: allocation-free rule) -------------
__device__ __nv_bfloat16 g_xhi[(size_t)DIM * DIM];
__device__ __nv_bfloat16 g_xlo[(size_t)DIM * DIM];
__device__ __nv_bfloat16 g_whi[(size_t)DIM * DIM];
__device__ __nv_bfloat16 g_wlo[(size_t)DIM * DIM];
__device__ __nv_bfloat16 g_ghi[(size_t)DIM * DIM];
__device__ __nv_bfloat16 g_glo[(size_t)DIM * DIM];
__device__ __nv_bfloat16 g_hhi[(size_t)DIM * DIM];
__device__ __nv_bfloat16 g_hlo[(size_t)DIM * DIM];

// ---------------- PTX helpers (sm_80-baseline features only) -----------------
static __device__ __forceinline__ uint32_t smem_u32(const void* p) {
    uint32_t a;
    asm("{ .reg .u64 t; cvta.to.shared.u64 t, %1; cvt.u32.u64 %0, t; }"
        : "=r"(a) : "l"(p));
    return a;
}

static __device__ __forceinline__ void cp16(uint32_t d, const void* g) {
    asm volatile("cp.async.cg.shared.global [%0], [%1], 16;" :: "r"(d), "l"(g) : "memory");
}

static __device__ __forceinline__ void ldsm4(uint32_t& r0, uint32_t& r1,
                                             uint32_t& r2, uint32_t& r3, uint32_t a) {
    asm volatile("ldmatrix.sync.aligned.m8n8.x4.shared.b16 {%0,%1,%2,%3}, [%4];"
                 : "=r"(r0), "=r"(r1), "=r"(r2), "=r"(r3) : "r"(a));
}

#define MMA16816(acc, a, b0, b1)                                                \
    asm volatile("mma.sync.aligned.m16n8k16.row.col.f32.bf16.bf16.f32 "         \
                 "{%0,%1,%2,%3}, {%4,%5,%6,%7}, {%8,%9}, {%0,%1,%2,%3};"        \
                 : "+f"((acc)[0]), "+f"((acc)[1]), "+f"((acc)[2]), "+f"((acc)[3])\
                 : "r"((a)[0]), "r"((a)[1]), "r"((a)[2]), "r"((a)[3]),          \
                   "r"(b0), "r"(b1))

#define MBAR_INIT(addr, cnt) \
    asm volatile("mbarrier.init.shared.b64 [%0], %1;" :: "r"(addr), "r"(cnt) : "memory")
#define MBAR_ARRIVE(addr) \
    asm volatile("{ .reg .b64 t; mbarrier.arrive.shared.b64 t, [%0]; }" :: "r"(addr) : "memory")
#define CP_ASYNC_ARRIVE(addr) \
    asm volatile("cp.async.mbarrier.arrive.noinc.shared.b64 [%0];" :: "r"(addr) : "memory")
#define MBAR_WAIT(addr, ph) do {                                                         \
    asm volatile("{\n\t.reg .pred P;\n\t"                                                \
                 "MW_%=:\n\t"                                                            \
                 "mbarrier.try_wait.parity.acquire.cta.shared::cta.b64 P, [%0], %1, 0x989680;\n\t" \
                 "@!P bra MW_%=;\n\t}"                                                   \
                 :: "r"(addr), "r"(ph) : "memory");                                      \
} while (0)

// SW64 swizzle for 64B rows: bo ^ ((bo>>3) & 0x30)

// Load one 128-row x 32-bf16 (64B/row) tile into SW64-swizzled SMEM.
static __device__ __forceinline__ void load_tile(uint32_t tb,
                                                 const __nv_bfloat16* __restrict__ src,
                                                 int r0, int k0, int tid) {
#pragma unroll
    for (int i = 0; i < 2; ++i) {
        int q = tid + i * 256;           // 512 16B chunks per tile
        int r = q >> 2, j = q & 3;
        const __nv_bfloat16* gp = src + (size_t)(r0 + r) * DIM + (k0 + j * 8);
        uint32_t bo = (uint32_t)(r * 64 + j * 16);
        cp16(tb + (bo ^ ((bo >> 3) & 0x30u)), gp);
    }
}

// Fill one full stage (4 tiles) + async-arrive on the stage's full barrier.
static __device__ __forceinline__ void fill_stage(
    uint32_t sb, int k0,
    const __nv_bfloat16* __restrict__ Ahi, const __nv_bfloat16* __restrict__ Alo,
    const __nv_bfloat16* __restrict__ Bhi, const __nv_bfloat16* __restrict__ Blo,
    int m0, int n0, int tid, uint32_t full_mb) {
    load_tile(sb,                  Ahi, m0, k0, tid);
    load_tile(sb + TILE_BYTES,     Alo, m0, k0, tid);
    load_tile(sb + 2 * TILE_BYTES, Bhi, n0, k0, tid);
    load_tile(sb + 3 * TILE_BYTES, Blo, n0, k0, tid);
    CP_ASYNC_ARRIVE(full_mb);
}

// One K-iteration of MMAs on a resident stage.
static __device__ __forceinline__ void mma_stage(
    uint32_t sb, uint32_t ccol,
    const uint32_t* arow_term, const uint32_t* axor,
    const uint32_t* brow_term, const uint32_t* bxor,
    float acc[4][4][4]) {
    const uint32_t sAhi = sb;
    const uint32_t sAlo = sb + TILE_BYTES;
    const uint32_t sBhi = sb + 2 * TILE_BYTES;
    const uint32_t sBlo = sb + 3 * TILE_BYTES;
#pragma unroll
    for (int s = 0; s < 2; ++s) {                      // 2 x K=16 per BK=32
        const uint32_t cs = ccol + (uint32_t)(s * 32);
        uint32_t bh[2][4], bl[2][4];
#pragma unroll
        for (int p = 0; p < 2; ++p) {
            uint32_t off = brow_term[p] + (cs ^ bxor[p]);
            ldsm4(bh[p][0], bh[p][1], bh[p][2], bh[p][3], sBhi + off);
            ldsm4(bl[p][0], bl[p][1], bl[p][2], bl[p][3], sBlo + off);
        }
#pragma unroll
        for (int f = 0; f < 4; ++f) {
            uint32_t off = arow_term[f] + (cs ^ axor[f]);
            uint32_t ah[4], al[4];
            ldsm4(ah[0], ah[1], ah[2], ah[3], sAhi + off);
            ldsm4(al[0], al[1], al[2], al[3], sAlo + off);
#pragma unroll
            for (int nf = 0; nf < 4; ++nf) {
                const int p = nf >> 1, o = nf & 1;
                const uint32_t bh0 = bh[p][o], bh1 = bh[p][o + 2];
                const uint32_t bl0 = bl[p][o], bl1 = bl[p][o + 2];
                MMA16816(acc[f][nf], ah, bh0, bh1);
                MMA16816(acc[f][nf], ah, bl0, bl1);
                MMA16816(acc[f][nf], al, bh0, bh1);
            }
        }
    }
}

// ---------------- fused GEMM: D = Ahi*Bhi^T + Ahi*Blo^T + Alo*Bhi^T ----------
// MODE 0: epilogue h = acc + bias; write bf16 hi/lo split (for second GEMM)
// MODE 1: epilogue z = acc + bias; c = cos(z); flip if |c| < EPS; write fp32
template <int MODE>
__global__ void __launch_bounds__(256, 2)
fused_gemm(const __nv_bfloat16* __restrict__ Ahi, const __nv_bfloat16* __restrict__ Alo,
           const __nv_bfloat16* __restrict__ Bhi, const __nv_bfloat16* __restrict__ Blo,
           const float* __restrict__ bias,
           float* __restrict__ outF,
           __nv_bfloat16* __restrict__ outHi, __nv_bfloat16* __restrict__ outLo) {
    extern __shared__ __align__(1024) char smem_raw[];
    const uint32_t sbase = smem_u32(smem_raw);
    const uint32_t s0 = sbase;
    const uint32_t s1 = sbase + STAGE_BYTES;
    const uint32_t s2 = sbase + 2 * STAGE_BYTES;
    // mbarriers: full0..2, empty0..2
    const uint32_t mbF0 = sbase + SMEM_STAGES;
    const uint32_t mbF1 = mbF0 + 8, mbF2 = mbF0 + 16;
    const uint32_t mbE0 = mbF0 + 24, mbE1 = mbF0 + 32, mbE2 = mbF0 + 40;

    const int tid  = threadIdx.x;
    const int wid  = tid >> 5;
    const int lane = tid & 31;

    // L2-friendly rasterization: groups of 8 M-tiles sweep across N
    const int GRID_N = DIM / BN;       // 32
    const int GROUP  = 8;
    const int width  = GROUP * GRID_N; // 256
    int pid  = blockIdx.x;
    int gidx = pid / width;
    int pin  = pid % width;
    const int m0 = (gidx * GROUP + (pin % GROUP)) * BM;
    const int n0 = (pin / GROUP) * BN;

    // warp layout: 2 (M) x 4 (N); warp tile 64 x 32
    const int wm = wid >> 2;
    const int wn = wid & 3;
    const int lr = lane & 15;
    const uint32_t ccol = (uint32_t)((lane >> 4) * 16);

    uint32_t arow_term[4], axor[4];
#pragma unroll
    for (int f = 0; f < 4; ++f) {
        int ar = wm * 64 + f * 16 + lr;
        arow_term[f] = (uint32_t)(ar * 64);
        axor[f] = (uint32_t)(((ar >> 1) & 3) << 4);
    }
    uint32_t brow_term[2], bxor[2];
#pragma unroll
    for (int p = 0; p < 2; ++p) {
        int br = wn * 32 + p * 16 + lr;
        brow_term[p] = (uint32_t)(br * 64);
        bxor[p] = (uint32_t)(((br >> 1) & 3) << 4);
    }

    float acc[4][4][4];
#pragma unroll
    for (int f = 0; f < 4; ++f)
#pragma unroll
        for (int nf = 0; nf < 4; ++nf)
#pragma unroll
            for (int e = 0; e < 4; ++e) acc[f][nf][e] = 0.0f;

    if (tid == 0) {
        MBAR_INIT(mbF0, 256u); MBAR_INIT(mbF1, 256u); MBAR_INIT(mbF2, 256u);
        MBAR_INIT(mbE0, 256u); MBAR_INIT(mbE1, 256u); MBAR_INIT(mbE2, 256u);
    }
    __syncthreads();   // init visible before any arrivals

    // prologue: fill stages 0 and 1 (fill index f=0; no empty wait)
    fill_stage(s0, 0,  Ahi, Alo, Bhi, Blo, m0, n0, tid, mbF0);
    fill_stage(s1, BK, Ahi, Alo, Bhi, Blo, m0, n0, tid, mbF1);

    // 42 rounds x 3 iterations; phase parities are (r&1)-derived.
    // it=3r  : consume s0 (full parity r&1), prefetch s2 fill f=r
    // it=3r+1: consume s1, prefetch s0 fill f=r+1 (empty parity r&1)
    // it=3r+2: consume s2, prefetch s1 fill f=r+1 (empty parity r&1)
    for (int r = 0; r < NROUND; ++r) {
        const uint32_t P  = (uint32_t)(r & 1);
        const uint32_t Pn = P ^ 1u;
        const int kb = 3 * r * BK;

        MBAR_WAIT(mbF0, P);
        mma_stage(s0, ccol, arow_term, axor, brow_term, bxor, acc);
        MBAR_ARRIVE(mbE0);
        if (r >= 1) MBAR_WAIT(mbE2, Pn);          // readers of fill r-1 done
        fill_stage(s2, kb + 2 * BK, Ahi, Alo, Bhi, Blo, m0, n0, tid, mbF2);

        MBAR_WAIT(mbF1, P);
        mma_stage(s1, ccol, arow_term, axor, brow_term, bxor, acc);
        MBAR_ARRIVE(mbE1);
        MBAR_WAIT(mbE0, P);
        fill_stage(s0, kb + 3 * BK, Ahi, Alo, Bhi, Blo, m0, n0, tid, mbF0);

        MBAR_WAIT(mbF2, P);
        mma_stage(s2, ccol, arow_term, axor, brow_term, bxor, acc);
        MBAR_ARRIVE(mbE2);
        MBAR_WAIT(mbE1, P);
        fill_stage(s1, kb + 4 * BK, Ahi, Alo, Bhi, Blo, m0, n0, tid, mbF1);
    }
    // tail: iterations 126 (s0) and 127 (s1); full parity = (42)&1 = 0
    MBAR_WAIT(mbF0, 0u);
    mma_stage(s0, ccol, arow_term, axor, brow_term, bxor, acc);
    MBAR_WAIT(mbF1, 0u);
    mma_stage(s1, ccol, arow_term, axor, brow_term, bxor, acc);

    // ---------------- epilogue (register -> global) --------------------------
    const int qrow = lane >> 2;            // 0..7
    const int qcol = (lane & 3) * 2;       // 0,2,4,6
#pragma unroll
    for (int f = 0; f < 4; ++f) {
#pragma unroll
        for (int nf = 0; nf < 4; ++nf) {
            const int col  = n0 + wn * 32 + nf * 8 + qcol;
            const int row0 = m0 + wm * 64 + f * 16 + qrow;
            const float2 bb = *reinterpret_cast<const float2*>(bias + col);
            float v00 = acc[f][nf][0] + bb.x;
            float v01 = acc[f][nf][1] + bb.y;
            float v10 = acc[f][nf][2] + bb.x;
            float v11 = acc[f][nf][3] + bb.y;
            size_t gi0 = (size_t)row0 * DIM + col;
            size_t gi1 = gi0 + (size_t)8 * DIM;
            if (MODE == 0) {
                __nv_bfloat16 h00 = __float2bfloat16(v00);
                __nv_bfloat16 h01 = __float2bfloat16(v01);
                __nv_bfloat16 h10 = __float2bfloat16(v10);
                __nv_bfloat16 h11 = __float2bfloat16(v11);
                __nv_bfloat162 hp0; hp0.x = h00; hp0.y = h01;
                __nv_bfloat162 hp1; hp1.x = h10; hp1.y = h11;
                __nv_bfloat162 lp0;
                lp0.x = __float2bfloat16(v00 - __bfloat162float(h00));
                lp0.y = __float2bfloat16(v01 - __bfloat162float(h01));
                __nv_bfloat162 lp1;
                lp1.x = __float2bfloat16(v10 - __bfloat162float(h10));
                lp1.y = __float2bfloat16(v11 - __bfloat162float(h11));
                *reinterpret_cast<__nv_bfloat162*>(outHi + gi0) = hp0;
                *reinterpret_cast<__nv_bfloat162*>(outHi + gi1) = hp1;
                *reinterpret_cast<__nv_bfloat162*>(outLo + gi0) = lp0;
                *reinterpret_cast<__nv_bfloat162*>(outLo + gi1) = lp1;
            } else {
                float c00 = cosf(v00); c00 = (fabsf(c00) < EPSF) ? -c00 : c00;
                float c01 = cosf(v01); c01 = (fabsf(c01) < EPSF) ? -c01 : c01;
                float c10 = cosf(v10); c10 = (fabsf(c10) < EPSF) ? -c10 : c10;
                float c11 = cosf(v11); c11 = (fabsf(c11) < EPSF) ? -c11 : c11;
                float2 o0 = make_float2(c00, c01);
                float2 o1 = make_float2(c10, c11);
                *reinterpret_cast<float2*>(outF + gi0) = o0;
                *reinterpret_cast<float2*>(outF + gi1) = o1;
            }
        }
    }
}

// ---------------- fp32 -> bf16 hi/lo splitter --------------------------------
__global__ void __launch_bounds__(256) split_bf16x2(
    const float* __restrict__ src, __nv_bfloat16* __restrict__ hi,
    __nv_bfloat16* __restrict__ lo, int n4) {
    int i = blockIdx.x * blockDim.x + threadIdx.x;
    if (i >= n4) return;
    float4 v = reinterpret_cast<const float4*>(src)[i];
    __nv_bfloat16 h0 = __float2bfloat16(v.x);
    __nv_bfloat16 h1 = __float2bfloat16(v.y);
    __nv_bfloat16 h2 = __float2bfloat16(v.z);
    __nv_bfloat16 h3 = __float2bfloat16(v.w);
    __nv_bfloat16 l0 = __float2bfloat16(v.x - __bfloat162float(h0));
    __nv_bfloat16 l1 = __float2bfloat16(v.y - __bfloat162float(h1));
    __nv_bfloat16 l2 = __float2bfloat16(v.z - __bfloat162float(h2));
    __nv_bfloat16 l3 = __float2bfloat16(v.w - __bfloat162float(h3));
    uint2 hp, lp;
    hp.x = (uint32_t)__bfloat16_as_ushort(h0) | ((uint32_t)__bfloat16_as_ushort(h1) << 16);
    hp.y = (uint32_t)__bfloat16_as_ushort(h2) | ((uint32_t)__bfloat16_as_ushort(h3) << 16);
    lp.x = (uint32_t)__bfloat16_as_ushort(l0) | ((uint32_t)__bfloat16_as_ushort(l1) << 16);
    lp.y = (uint32_t)__bfloat16_as_ushort(l2) | ((uint32_t)__bfloat16_as_ushort(l3) << 16);
    reinterpret_cast<uint2*>(hi)[i] = hp;
    reinterpret_cast<uint2*>(lo)[i] = lp;
}

// ---------------- launch -----------------------------------------------------
extern "C" void kernel_launch(void* const* d_in, const int* in_sizes, int n_in,
                              void* d_out, int out_size) {
    const float* x  = (const float*)d_in[0];
    const float* W  = (const float*)d_in[1];
    const float* b  = (const float*)d_in[2];
    const float* g  = (const float*)d_in[3];
    const float* gb = (const float*)d_in[4];
    float* out = (float*)d_out;

    __nv_bfloat16 *xhi, *xlo, *whi, *wlo, *ghi, *glo, *hhi, *hlo;
    cudaGetSymbolAddress((void**)&xhi, g_xhi);
    cudaGetSymbolAddress((void**)&xlo, g_xlo);
    cudaGetSymbolAddress((void**)&whi, g_whi);
    cudaGetSymbolAddress((void**)&wlo, g_wlo);
    cudaGetSymbolAddress((void**)&ghi, g_ghi);
    cudaGetSymbolAddress((void**)&glo, g_glo);
    cudaGetSymbolAddress((void**)&hhi, g_hhi);
    cudaGetSymbolAddress((void**)&hlo, g_hlo);

    const int n4 = (int)((size_t)DIM * DIM / 4);   // 4,194,304
    split_bf16x2<<<n4 / 256, 256>>>(x, xhi, xlo, n4);
    split_bf16x2<<<n4 / 256, 256>>>(W, whi, wlo, n4);
    split_bf16x2<<<n4 / 256, 256>>>(g, ghi, glo, n4);

    cudaFuncSetAttribute(fused_gemm<0>, cudaFuncAttributeMaxDynamicSharedMemorySize, SMEM_DYN);
    cudaFuncSetAttribute(fused_gemm<1>, cudaFuncAttributeMaxDynamicSharedMemorySize, SMEM_DYN);

    const int grid = (DIM / BM) * (DIM / BN);      // 1024
    fused_gemm<0><<<grid, 256, SMEM_DYN>>>(xhi, xlo, whi, wlo, b, nullptr, hhi, hlo);
    fused_gemm<1><<<grid, 256, SMEM_DYN>>>(hhi, hlo, ghi, glo, gb, out, nullptr, nullptr);
}